// round 15
// baseline (speedup 1.0000x reference)
#include <cuda_runtime.h>
#include <cuda_bf16.h>
#include <cstdint>

#define B_DIM 4096
#define D_DIM 1024
#define H1_DIM 128
#define H2_DIM 64
#define O_DIM 2
#define KSPLIT 4
#define KCHUNK (D_DIM / KSPLIT)   // 256

// Scratch (no cudaMalloc allowed)
__device__ float g_partT[KSPLIT * H1_DIM * B_DIM]; // gemm1 partials, TRANSPOSED [z][f][b]
__device__ float g_pr0T[H1_DIM * B_DIM];           // knn output transposed [f][b]

// ---------------------------------------------------------------------------
// Packed fp32x2 helpers (Blackwell FFMA2 — only reachable via PTX)
// ---------------------------------------------------------------------------
__device__ __forceinline__ unsigned long long pk2(float x, float y) {
    unsigned long long r;
    asm("mov.b64 %0, {%1, %2};" : "=l"(r) : "f"(x), "f"(y));
    return r;
}
__device__ __forceinline__ void ffma2(unsigned long long& d,
                                      unsigned long long a,
                                      unsigned long long b) {
    asm("fma.rn.f32x2 %0, %1, %2, %0;" : "+l"(d) : "l"(a), "l"(b));
}
__device__ __forceinline__ float2 upk2(unsigned long long v) {
    float2 f;
    asm("mov.b64 {%0, %1}, %2;" : "=f"(f.x), "=f"(f.y) : "l"(v));
    return f;
}

// ---------------------------------------------------------------------------
// Pipelined SGEMM with FFMA2 (NN): gemm1 K-split, TRANSPOSED output.
// BM=32, BN=64, BK=32, 128 threads. grid=(M/32, N/64, KSPLIT).
// Each z computes K-chunk [z*Kloop, (z+1)*Kloop); epilogue stores the raw
// partial transposed into CT + z*N_total*M  (layout [z][n][m]).
// ---------------------------------------------------------------------------
__global__ __launch_bounds__(128) void gemm_split_kernel(
    const float* __restrict__ A, const float* __restrict__ Bm,
    float* __restrict__ CT, int M, int N, int Kloop, int lda)
{
    constexpr int BM = 32, BK = 32;
    __shared__ float As[BM][BK + 1];
    __shared__ float Bs[BK][68];

    const int tid = threadIdx.x;
    const int tx = tid & 7;
    const int ty = tid >> 3;
    const int row0 = blockIdx.x * BM;
    const int col0 = blockIdx.y * 64;
    const int z = blockIdx.z;

    const float* Ap = A + (size_t)z * Kloop;
    const float* Bp = Bm + (size_t)col0 * lda + (size_t)z * Kloop;
    float* CzT = CT + (size_t)z * N * M;   // [n][m]

    const int l_kq = tid & 7;
    const int l_r  = tid >> 3;

    unsigned long long acc[2][4];
#pragma unroll
    for (int i = 0; i < 2; i++)
#pragma unroll
        for (int j = 0; j < 4; j++) acc[i][j] = 0ull;

    const int NB = Kloop / BK;
    float4 pa[2], pb[4];

#pragma unroll
    for (int it = 0; it < 2; it++)
        pa[it] = *(const float4*)&Ap[(size_t)(row0 + l_r + it * 16) * lda + l_kq * 4];
#pragma unroll
    for (int it = 0; it < 4; it++)
        pb[it] = *(const float4*)&Bp[(size_t)(l_r + it * 16) * lda + l_kq * 4];

#pragma unroll
    for (int it = 0; it < 2; it++) {
        int r = l_r + it * 16;
        As[r][l_kq * 4 + 0] = pa[it].x; As[r][l_kq * 4 + 1] = pa[it].y;
        As[r][l_kq * 4 + 2] = pa[it].z; As[r][l_kq * 4 + 3] = pa[it].w;
    }
#pragma unroll
    for (int it = 0; it < 4; it++) {
        int f = l_r + it * 16;
        Bs[l_kq * 4 + 0][f] = pb[it].x; Bs[l_kq * 4 + 1][f] = pb[it].y;
        Bs[l_kq * 4 + 2][f] = pb[it].z; Bs[l_kq * 4 + 3][f] = pb[it].w;
    }
    __syncthreads();

    const int ty2 = ty * 2;
    for (int kb = 0; kb < NB; kb++) {
        const bool more = (kb + 1 < NB);
        if (more) {
            const int k0 = (kb + 1) * BK;
#pragma unroll
            for (int it = 0; it < 2; it++)
                pa[it] = *(const float4*)&Ap[(size_t)(row0 + l_r + it * 16) * lda + k0 + l_kq * 4];
#pragma unroll
            for (int it = 0; it < 4; it++)
                pb[it] = *(const float4*)&Bp[(size_t)(l_r + it * 16) * lda + k0 + l_kq * 4];
        }

#pragma unroll
        for (int kk = 0; kk < BK; kk++) {
            float a0 = As[ty2][kk];
            float a1 = As[ty2 + 1][kk];
            unsigned long long ap0 = pk2(a0, a0);
            unsigned long long ap1 = pk2(a1, a1);
            ulonglong2 b01 = *(const ulonglong2*)&Bs[kk][tx * 4];
            ulonglong2 b23 = *(const ulonglong2*)&Bs[kk][32 + tx * 4];
            ffma2(acc[0][0], ap0, b01.x); ffma2(acc[0][1], ap0, b01.y);
            ffma2(acc[0][2], ap0, b23.x); ffma2(acc[0][3], ap0, b23.y);
            ffma2(acc[1][0], ap1, b01.x); ffma2(acc[1][1], ap1, b01.y);
            ffma2(acc[1][2], ap1, b23.x); ffma2(acc[1][3], ap1, b23.y);
        }
        __syncthreads();
        if (more) {
#pragma unroll
            for (int it = 0; it < 2; it++) {
                int r = l_r + it * 16;
                As[r][l_kq * 4 + 0] = pa[it].x; As[r][l_kq * 4 + 1] = pa[it].y;
                As[r][l_kq * 4 + 2] = pa[it].z; As[r][l_kq * 4 + 3] = pa[it].w;
            }
#pragma unroll
            for (int it = 0; it < 4; it++) {
                int f = l_r + it * 16;
                Bs[l_kq * 4 + 0][f] = pb[it].x; Bs[l_kq * 4 + 1][f] = pb[it].y;
                Bs[l_kq * 4 + 2][f] = pb[it].z; Bs[l_kq * 4 + 3][f] = pb[it].w;
            }
            __syncthreads();
        }
    }

    // Transposed epilogue: per column c store float2 {row ty2, row ty2+1}
#pragma unroll
    for (int half = 0; half < 2; half++) {
#pragma unroll
        for (int q = 0; q < 2; q++) {
            const int c0 = col0 + half * 32 + tx * 4 + 2 * q;
            float2 r0 = upk2(acc[0][half * 2 + q]);   // cols c0, c0+1 of row ty2
            float2 r1 = upk2(acc[1][half * 2 + q]);   // cols c0, c0+1 of row ty2+1
            *(float2*)&CzT[(size_t)c0 * M + row0 + ty2] = make_float2(r0.x, r1.x);
            *(float2*)&CzT[(size_t)(c0 + 1) * M + row0 + ty2] = make_float2(r0.y, r1.y);
        }
    }
}

// ---------------------------------------------------------------------------
// Per-feature 6-NN batch averaging, fused with the K-split combine.
// partT layout [z][f][b]: the 4 partial rows for feature f are coalesced.
// h1 = relu(p0+p1+p2+p3 + b1[f]) (fixed order -> deterministic).
// Hybrid bitonic sort (registers / shuffles / smem), rank via binary search,
// greedy frontier walk for the 6-NN mean. One CTA per feature.
// ---------------------------------------------------------------------------
__device__ __forceinline__ void ce_u32(unsigned int& a, unsigned int& b, bool up) {
    unsigned int mn = min(a, b), mx = max(a, b);
    a = up ? mn : mx;
    b = up ? mx : mn;
}

__global__ __launch_bounds__(1024) void knn_mean_kernel(
    const float* __restrict__ partT, const float* __restrict__ b1,
    float* __restrict__ outT)
{
    __shared__ unsigned int sv[B_DIM];  // 16 KB

    const int f = blockIdx.x;
    const int t = threadIdx.x;
    const int lane = t & 31;
    const unsigned int i0 = 4u * (unsigned)t;
    const float biasf = b1[f];
    const size_t ZS = (size_t)H1_DIM * B_DIM;
    const size_t base = (size_t)f * B_DIM + i0;

    unsigned int v[4], myv[4];
    {
        float4 s0 = *(const float4*)&partT[base];
        float4 s1 = *(const float4*)&partT[base + ZS];
        float4 s2 = *(const float4*)&partT[base + 2 * ZS];
        float4 s3 = *(const float4*)&partT[base + 3 * ZS];
        float h0 = fmaxf(s0.x + s1.x + s2.x + s3.x + biasf, 0.0f);
        float h1 = fmaxf(s0.y + s1.y + s2.y + s3.y + biasf, 0.0f);
        float h2 = fmaxf(s0.z + s1.z + s2.z + s3.z + biasf, 0.0f);
        float h3 = fmaxf(s0.w + s1.w + s2.w + s3.w + biasf, 0.0f);
        v[0] = __float_as_uint(h0); v[1] = __float_as_uint(h1);
        v[2] = __float_as_uint(h2); v[3] = __float_as_uint(h3);
#pragma unroll
        for (int e = 0; e < 4; e++) myv[e] = v[e];
    }

    {
        if (v[0] > v[1]) { unsigned int tm = v[0]; v[0] = v[1]; v[1] = tm; }
        if (v[2] < v[3]) { unsigned int tm = v[2]; v[2] = v[3]; v[3] = tm; }
    }
    {
        bool up = (t & 1) == 0;
        ce_u32(v[0], v[2], up); ce_u32(v[1], v[3], up);
        ce_u32(v[0], v[1], up); ce_u32(v[2], v[3], up);
    }

    for (unsigned int k = 8; k <= B_DIM; k <<= 1) {
        const bool up = ((i0 & k) == 0);
        unsigned int j = k >> 1;

        if (j >= 128) {
            *(uint4*)&sv[i0] = make_uint4(v[0], v[1], v[2], v[3]);
            __syncthreads();
            for (; j >= 128; j >>= 1) {
#pragma unroll 2
                for (int p = t; p < B_DIM / 2; p += 1024) {
                    int i = ((p & ~(int)(j - 1)) << 1) | (p & (int)(j - 1));
                    int ixj = i | (int)j;
                    unsigned int a = sv[i];
                    unsigned int b = sv[ixj];
                    bool u2 = ((i & (int)k) == 0);
                    if (u2 ? (a > b) : (a < b)) { sv[i] = b; sv[ixj] = a; }
                }
                __syncthreads();
            }
            uint4 u = *(const uint4*)&sv[i0];
            v[0] = u.x; v[1] = u.y; v[2] = u.z; v[3] = u.w;
        }

        for (; j >= 4; j >>= 1) {
            const unsigned int d = j >> 2;
            const bool keepmin = (up == ((lane & d) == 0));
#pragma unroll
            for (int e = 0; e < 4; e++) {
                unsigned int o = __shfl_xor_sync(0xFFFFFFFFu, v[e], d);
                unsigned int mn = min(v[e], o), mx = max(v[e], o);
                v[e] = keepmin ? mn : mx;
            }
        }

        ce_u32(v[0], v[2], up); ce_u32(v[1], v[3], up);
        ce_u32(v[0], v[1], up); ce_u32(v[2], v[3], up);
    }

    *(uint4*)&sv[i0] = make_uint4(v[0], v[1], v[2], v[3]);
    __syncthreads();

    const float BIG = __int_as_float(0x7f000000);
    float res[4];

#pragma unroll
    for (int e = 0; e < 4; e++) {
        const unsigned int vb = myv[e];
        int lo = 0, hi = B_DIM;
#pragma unroll
        for (int s = 0; s < 12; s++) {
            int mid = (lo + hi) >> 1;
            if (sv[mid] < vb) lo = mid + 1; else hi = mid;
        }
        int p = lo;
        float val = __uint_as_float(vb);
        float sum = val;
        int l = p - 1, r = p + 1;
#pragma unroll
        for (int s = 0; s < 5; s++) {
            float vl = (l >= 0)     ? __uint_as_float(sv[l]) : 0.0f;
            float vr = (r < B_DIM)  ? __uint_as_float(sv[r]) : 0.0f;
            float dl = (l >= 0)     ? (val - vl) : BIG;
            float dr = (r < B_DIM)  ? (vr - val) : BIG;
            if (dl <= dr) { sum += vl; l--; }
            else          { sum += vr; r++; }
        }
        res[e] = sum * (1.0f / 6.0f);
    }

    *(float4*)&outT[(size_t)f * B_DIM + i0] =
        make_float4(res[0], res[1], res[2], res[3]);
}

// ---------------------------------------------------------------------------
// Fully fused PR tail, 256 threads (8 warps -> 2 warps/SMSP latency cover):
//   pr1 = relu(pr0T^T @ Wpr^T + bpr)   (TN gemm, BM=32, BN=128 = all cols)
//   h2  = relu(pr1 @ W2^T + b2)        (in-CTA, chunked W2, FFMA2)
//   out = h2 @ Wo^T + bo
// 128 CTAs. Shared memory phase-aliased through one pool.
// ---------------------------------------------------------------------------
__global__ __launch_bounds__(256) void pr_tail_fused_kernel(
    const float* __restrict__ AT,    // pr0T [128][4096]
    const float* __restrict__ Wpr,   // [128][128] K-major
    const float* __restrict__ bpr,   // [128]
    const float* __restrict__ W2,    // [64][128]
    const float* __restrict__ b2,    // [64]
    const float* __restrict__ Wo,    // [2,64]
    const float* __restrict__ bo,    // [2]
    float* __restrict__ out)         // [4096,2]
{
    constexpr int BM = 32, BK = 32, K = H1_DIM, M = B_DIM, NB = K / BK;

    // Pool: phase1 As2[32][34] (4352 B) + Bs[32][132] (16896 B) = 21248 B
    //       phase2 prs[32][132] (16896) + w2c[32][68] (8704) + h2s[32][65] (8320)
    __shared__ __align__(16) char pool[33920];
    float (*As2)[34]  = (float(*)[34])pool;                  // [k][m]
    float (*Bs)[132]  = (float(*)[132])(pool + 4352);        // [k][n]
    float (*prs)[132] = (float(*)[132])pool;                 // pr1 tile [m][k]
    float (*w2c)[68]  = (float(*)[68])(pool + 16896);        // W2 chunk [k][c]
    float (*h2s)[65]  = (float(*)[65])(pool + 25600);        // h2 tile
    __shared__ float wos[O_DIM * H2_DIM];
    __shared__ float bprs[H1_DIM];
    __shared__ float b2s[H2_DIM];
    __shared__ float bos[O_DIM];

    const int tid = threadIdx.x;
    const int tx = tid & 7;        // col group (8)
    const int ty = tid >> 3;       // row 0..31 (one row per thread)
    const int row0 = blockIdx.x * BM;
    const int l_kq = tid & 7;
    const int l_r  = tid >> 3;     // 0..31

    if (tid < O_DIM * H2_DIM) wos[tid] = Wo[tid];
    if (tid < H1_DIM) bprs[tid] = bpr[tid];
    if (tid < H2_DIM) b2s[tid] = b2[tid];
    if (tid < O_DIM)  bos[tid] = bo[tid];

    unsigned long long acc[8];
#pragma unroll
    for (int j = 0; j < 8; j++) acc[j] = 0ull;

    float4 pa, pb[4];
    pa = *(const float4*)&AT[(size_t)l_r * M + row0 + l_kq * 4];
#pragma unroll
    for (int it = 0; it < 4; it++)
        pb[it] = *(const float4*)&Wpr[(size_t)(l_r + it * 32) * K + l_kq * 4];

    {
        As2[l_r][l_kq * 4 + 0] = pa.x; As2[l_r][l_kq * 4 + 1] = pa.y;
        As2[l_r][l_kq * 4 + 2] = pa.z; As2[l_r][l_kq * 4 + 3] = pa.w;
#pragma unroll
        for (int it = 0; it < 4; it++) {
            int f = l_r + it * 32;
            Bs[l_kq * 4 + 0][f] = pb[it].x; Bs[l_kq * 4 + 1][f] = pb[it].y;
            Bs[l_kq * 4 + 2][f] = pb[it].z; Bs[l_kq * 4 + 3][f] = pb[it].w;
        }
    }
    __syncthreads();

    for (int kb = 0; kb < NB; kb++) {
        const bool more = (kb + 1 < NB);
        if (more) {
            const int k0 = (kb + 1) * BK;
            pa = *(const float4*)&AT[(size_t)(k0 + l_r) * M + row0 + l_kq * 4];
#pragma unroll
            for (int it = 0; it < 4; it++)
                pb[it] = *(const float4*)&Wpr[(size_t)(l_r + it * 32) * K + k0 + l_kq * 4];
        }

#pragma unroll
        for (int kk = 0; kk < BK; kk++) {
            float a = As2[kk][ty];
            unsigned long long ap = pk2(a, a);
#pragma unroll
            for (int q = 0; q < 4; q++) {
                ulonglong2 bq = *(const ulonglong2*)&Bs[kk][q * 32 + tx * 4];
                ffma2(acc[q * 2 + 0], ap, bq.x);
                ffma2(acc[q * 2 + 1], ap, bq.y);
            }
        }
        __syncthreads();
        if (more) {
            As2[l_r][l_kq * 4 + 0] = pa.x; As2[l_r][l_kq * 4 + 1] = pa.y;
            As2[l_r][l_kq * 4 + 2] = pa.z; As2[l_r][l_kq * 4 + 3] = pa.w;
#pragma unroll
            for (int it = 0; it < 4; it++) {
                int f = l_r + it * 32;
                Bs[l_kq * 4 + 0][f] = pb[it].x; Bs[l_kq * 4 + 1][f] = pb[it].y;
                Bs[l_kq * 4 + 2][f] = pb[it].z; Bs[l_kq * 4 + 3][f] = pb[it].w;
            }
            __syncthreads();
        }
    }

    // pr1 row -> prs (aliases pool) with bias + ReLU
#pragma unroll
    for (int q = 0; q < 4; q++) {
        const int c = q * 32 + tx * 4;
        float2 p0 = upk2(acc[q * 2 + 0]);
        float2 p1 = upk2(acc[q * 2 + 1]);
        prs[ty][c + 0] = fmaxf(p0.x + bprs[c + 0], 0.0f);
        prs[ty][c + 1] = fmaxf(p0.y + bprs[c + 1], 0.0f);
        prs[ty][c + 2] = fmaxf(p1.x + bprs[c + 2], 0.0f);
        prs[ty][c + 3] = fmaxf(p1.y + bprs[c + 3], 0.0f);
    }
    __syncthreads();

    // h2 = relu(prs @ W2^T + b2): 256 threads, each 2 rows x 4 cols, FFMA2
    const int tx2 = tid & 15;   // cols tx2*4 .. +3
    const int tyB = tid >> 4;   // rows tyB*2, tyB*2+1
    unsigned long long acc2[2][2];
#pragma unroll
    for (int i = 0; i < 2; i++) { acc2[i][0] = 0ull; acc2[i][1] = 0ull; }

    for (int kb2 = 0; kb2 < 4; kb2++) {
        // load W2 chunk [64 c][32 k] transposed into w2c[k][c]
#pragma unroll
        for (int it = 0; it < 2; it++) {
            int c = l_r + it * 32;
            float4 w = *(const float4*)&W2[(size_t)c * K + kb2 * 32 + l_kq * 4];
            w2c[l_kq * 4 + 0][c] = w.x;
            w2c[l_kq * 4 + 1][c] = w.y;
            w2c[l_kq * 4 + 2][c] = w.z;
            w2c[l_kq * 4 + 3][c] = w.w;
        }
        __syncthreads();
#pragma unroll
        for (int kk = 0; kk < 32; kk++) {
            ulonglong2 wv = *(const ulonglong2*)&w2c[kk][tx2 * 4];
            float p0 = prs[tyB * 2 + 0][kb2 * 32 + kk];
            float p1 = prs[tyB * 2 + 1][kb2 * 32 + kk];
            unsigned long long a0 = pk2(p0, p0);
            unsigned long long a1 = pk2(p1, p1);
            ffma2(acc2[0][0], a0, wv.x); ffma2(acc2[0][1], a0, wv.y);
            ffma2(acc2[1][0], a1, wv.x); ffma2(acc2[1][1], a1, wv.y);
        }
        __syncthreads();
    }

    // h2s with bias + ReLU
#pragma unroll
    for (int i = 0; i < 2; i++) {
        float2 q0 = upk2(acc2[i][0]);
        float2 q1 = upk2(acc2[i][1]);
        const int c = tx2 * 4;
        h2s[tyB * 2 + i][c + 0] = fmaxf(q0.x + b2s[c + 0], 0.0f);
        h2s[tyB * 2 + i][c + 1] = fmaxf(q0.y + b2s[c + 1], 0.0f);
        h2s[tyB * 2 + i][c + 2] = fmaxf(q1.x + b2s[c + 2], 0.0f);
        h2s[tyB * 2 + i][c + 3] = fmaxf(q1.y + b2s[c + 3], 0.0f);
    }
    __syncthreads();

    // Projection: 64 work items (32 rows x 2 outs)
    if (tid < BM * O_DIM) {
        int r = tid >> 1, o = tid & 1;
        float s = 0.0f;
        const float* w = &wos[o * H2_DIM];
#pragma unroll
        for (int k = 0; k < H2_DIM; k++)
            s = fmaf(h2s[r][k], w[k], s);
        out[(size_t)(row0 + r) * O_DIM + o] = s + bos[o];
    }
}

// ---------------------------------------------------------------------------
extern "C" void kernel_launch(void* const* d_in, const int* in_sizes, int n_in,
                              void* d_out, int out_size)
{
    const float* x   = (const float*)d_in[0];
    const float* W1  = (const float*)d_in[1];
    const float* b1  = (const float*)d_in[2];
    const float* Wpr = (const float*)d_in[3];
    const float* bpr = (const float*)d_in[4];
    const float* W2  = (const float*)d_in[5];
    const float* b2  = (const float*)d_in[6];
    const float* Wo  = (const float*)d_in[7];
    const float* bo  = (const float*)d_in[8];
    float* out = (float*)d_out;

    float *partT, *pr0T;
    cudaGetSymbolAddress((void**)&partT, g_partT);
    cudaGetSymbolAddress((void**)&pr0T,  g_pr0T);

    // 1) gemm1 K-split, transposed partial output [z][f][b]  (1024 CTAs)
    gemm_split_kernel<<<dim3(B_DIM / 32, H1_DIM / 64, KSPLIT), 128>>>(
        x, W1, partT, B_DIM, H1_DIM, KCHUNK, D_DIM);
    // 2) knn: inline combine (+b1, relu) + 6-NN mean, all coalesced
    knn_mean_kernel<<<H1_DIM, 1024>>>(partT, b1, pr0T);
    // 3) fused pr1 + h2 + output projection (256 threads for latency cover)
    pr_tail_fused_kernel<<<B_DIM / 32, 256>>>(
        pr0T, Wpr, bpr, W2, b2, Wo, bo, out);
}

// round 16
// speedup vs baseline: 1.1931x; 1.1931x over previous
#include <cuda_runtime.h>
#include <cuda_bf16.h>
#include <cstdint>

#define B_DIM 4096
#define D_DIM 1024
#define H1_DIM 128
#define H2_DIM 64
#define O_DIM 2
#define KSPLIT 4
#define KCHUNK (D_DIM / KSPLIT)   // 256

// Scratch (no cudaMalloc allowed)
__device__ float g_part[KSPLIT * B_DIM * H1_DIM];  // gemm1 partials [z][b][f]
__device__ float g_h1T[H1_DIM * B_DIM];            // h1 transposed [f][b]
__device__ float g_pr0T[H1_DIM * B_DIM];           // knn output transposed [f][b]

// ---------------------------------------------------------------------------
// Packed fp32x2 helpers (Blackwell FFMA2 — only reachable via PTX)
// ---------------------------------------------------------------------------
__device__ __forceinline__ unsigned long long pk2(float x, float y) {
    unsigned long long r;
    asm("mov.b64 %0, {%1, %2};" : "=l"(r) : "f"(x), "f"(y));
    return r;
}
__device__ __forceinline__ void ffma2(unsigned long long& d,
                                      unsigned long long a,
                                      unsigned long long b) {
    asm("fma.rn.f32x2 %0, %1, %2, %0;" : "+l"(d) : "l"(a), "l"(b));
}
__device__ __forceinline__ float2 upk2(unsigned long long v) {
    float2 f;
    asm("mov.b64 {%0, %1}, %2;" : "=f"(f.x), "=f"(f.y) : "l"(v));
    return f;
}

// ---------------------------------------------------------------------------
// High-density SGEMM (NN) for gemm1 K-split.
// BM=64, BN=64, BK=32, 128 threads, 4 rows x 8 cols per thread.
// A staged TRANSPOSED in smem ([k][m], stride 68): the mainloop does
// 3 LDS.128 per 16 FFMA2 (vs 4 LDS per 8 before) — fixes the measured
// L1tex-bound profile (83.7% L1, 25.6% fma).
// grid = (M/64, N/64, KSPLIT); z stores raw partial to C + z*M*N (row-major,
// coalesced float4).
// ---------------------------------------------------------------------------
__global__ __launch_bounds__(128) void gemm_split_kernel(
    const float* __restrict__ A, const float* __restrict__ Bm,
    float* __restrict__ C, int M, int N, int Kloop, int lda)
{
    constexpr int BK = 32;
    __shared__ float As2[BK][68];   // [k][m] transposed
    __shared__ float Bs[BK][68];    // [k][n]

    const int tid = threadIdx.x;
    const int tx = tid & 7;         // 8 col groups
    const int ty = tid >> 3;        // 16 row groups -> rows ty*4 .. +3
    const int row0 = blockIdx.x * 64;
    const int col0 = blockIdx.y * 64;
    const int z = blockIdx.z;

    const float* Ap = A + (size_t)z * Kloop;
    const float* Bp = Bm + (size_t)col0 * lda + (size_t)z * Kloop;
    float* Cz = C + (size_t)z * M * N;

    const int l_kq = tid & 7;
    const int l_r  = tid >> 3;      // 0..15

    unsigned long long acc[4][4];
#pragma unroll
    for (int i = 0; i < 4; i++)
#pragma unroll
        for (int j = 0; j < 4; j++) acc[i][j] = 0ull;

    const int NB = Kloop / BK;
    float4 pa[4], pb[4];

#pragma unroll
    for (int it = 0; it < 4; it++)
        pa[it] = *(const float4*)&Ap[(size_t)(row0 + l_r + it * 16) * lda + l_kq * 4];
#pragma unroll
    for (int it = 0; it < 4; it++)
        pb[it] = *(const float4*)&Bp[(size_t)(l_r + it * 16) * lda + l_kq * 4];

#pragma unroll
    for (int it = 0; it < 4; it++) {
        int r = l_r + it * 16;
        As2[l_kq * 4 + 0][r] = pa[it].x; As2[l_kq * 4 + 1][r] = pa[it].y;
        As2[l_kq * 4 + 2][r] = pa[it].z; As2[l_kq * 4 + 3][r] = pa[it].w;
    }
#pragma unroll
    for (int it = 0; it < 4; it++) {
        int f = l_r + it * 16;
        Bs[l_kq * 4 + 0][f] = pb[it].x; Bs[l_kq * 4 + 1][f] = pb[it].y;
        Bs[l_kq * 4 + 2][f] = pb[it].z; Bs[l_kq * 4 + 3][f] = pb[it].w;
    }
    __syncthreads();

    for (int kb = 0; kb < NB; kb++) {
        const bool more = (kb + 1 < NB);
        if (more) {
            const int k0 = (kb + 1) * BK;
#pragma unroll
            for (int it = 0; it < 4; it++)
                pa[it] = *(const float4*)&Ap[(size_t)(row0 + l_r + it * 16) * lda + k0 + l_kq * 4];
#pragma unroll
            for (int it = 0; it < 4; it++)
                pb[it] = *(const float4*)&Bp[(size_t)(l_r + it * 16) * lda + k0 + l_kq * 4];
        }

#pragma unroll
        for (int kk = 0; kk < BK; kk++) {
            float4 a = *(const float4*)&As2[kk][ty * 4];       // 4 rows
            ulonglong2 b01 = *(const ulonglong2*)&Bs[kk][tx * 4];
            ulonglong2 b23 = *(const ulonglong2*)&Bs[kk][32 + tx * 4];
            unsigned long long ap0 = pk2(a.x, a.x);
            unsigned long long ap1 = pk2(a.y, a.y);
            unsigned long long ap2 = pk2(a.z, a.z);
            unsigned long long ap3 = pk2(a.w, a.w);
            ffma2(acc[0][0], ap0, b01.x); ffma2(acc[0][1], ap0, b01.y);
            ffma2(acc[0][2], ap0, b23.x); ffma2(acc[0][3], ap0, b23.y);
            ffma2(acc[1][0], ap1, b01.x); ffma2(acc[1][1], ap1, b01.y);
            ffma2(acc[1][2], ap1, b23.x); ffma2(acc[1][3], ap1, b23.y);
            ffma2(acc[2][0], ap2, b01.x); ffma2(acc[2][1], ap2, b01.y);
            ffma2(acc[2][2], ap2, b23.x); ffma2(acc[2][3], ap2, b23.y);
            ffma2(acc[3][0], ap3, b01.x); ffma2(acc[3][1], ap3, b01.y);
            ffma2(acc[3][2], ap3, b23.x); ffma2(acc[3][3], ap3, b23.y);
        }
        __syncthreads();
        if (more) {
#pragma unroll
            for (int it = 0; it < 4; it++) {
                int r = l_r + it * 16;
                As2[l_kq * 4 + 0][r] = pa[it].x; As2[l_kq * 4 + 1][r] = pa[it].y;
                As2[l_kq * 4 + 2][r] = pa[it].z; As2[l_kq * 4 + 3][r] = pa[it].w;
            }
#pragma unroll
            for (int it = 0; it < 4; it++) {
                int f = l_r + it * 16;
                Bs[l_kq * 4 + 0][f] = pb[it].x; Bs[l_kq * 4 + 1][f] = pb[it].y;
                Bs[l_kq * 4 + 2][f] = pb[it].z; Bs[l_kq * 4 + 3][f] = pb[it].w;
            }
            __syncthreads();
        }
    }

    // Row-major coalesced epilogue (raw partials, no bias)
#pragma unroll
    for (int r = 0; r < 4; r++) {
        const int row = row0 + ty * 4 + r;
#pragma unroll
        for (int half = 0; half < 2; half++) {
            const int c = col0 + half * 32 + tx * 4;
            float2 p0 = upk2(acc[r][half * 2 + 0]);
            float2 p1 = upk2(acc[r][half * 2 + 1]);
            *(float4*)&Cz[(size_t)row * N + c] =
                make_float4(p0.x, p0.y, p1.x, p1.y);
        }
    }
}

// ---------------------------------------------------------------------------
// Combine K-split partials + bias + ReLU, writing h1 TRANSPOSED:
// h1T[f][b] = relu(sum_z part_z[b][f] + b1[f]). Coalesced both sides.
// (Measured ~3us in the 84.7us run.)
// ---------------------------------------------------------------------------
__global__ __launch_bounds__(256) void combine_transpose_kernel(
    const float* __restrict__ part, const float* __restrict__ b1,
    float* __restrict__ h1T)
{
    __shared__ float t[32][33];
    const int bx = blockIdx.x * 32;
    const int fx = blockIdx.y * 32;
    const int tid = threadIdx.x;
    const int x = tid & 7;
    const int y = tid >> 3;

    const size_t BH = (size_t)B_DIM * H1_DIM;
    const size_t idx = (size_t)(bx + y) * H1_DIM + fx + x * 4;
    float4 s  = *(const float4*)&part[idx];
    float4 p1 = *(const float4*)&part[idx + BH];
    float4 p2 = *(const float4*)&part[idx + 2 * BH];
    float4 p3 = *(const float4*)&part[idx + 3 * BH];
    s.x += p1.x; s.y += p1.y; s.z += p1.z; s.w += p1.w;
    s.x += p2.x; s.y += p2.y; s.z += p2.z; s.w += p2.w;
    s.x += p3.x; s.y += p3.y; s.z += p3.z; s.w += p3.w;
    const float4 bv = *(const float4*)&b1[fx + x * 4];
    t[y][x * 4 + 0] = fmaxf(s.x + bv.x, 0.0f);
    t[y][x * 4 + 1] = fmaxf(s.y + bv.y, 0.0f);
    t[y][x * 4 + 2] = fmaxf(s.z + bv.z, 0.0f);
    t[y][x * 4 + 3] = fmaxf(s.w + bv.w, 0.0f);
    __syncthreads();

    float4 o;
    o.x = t[x * 4 + 0][y];
    o.y = t[x * 4 + 1][y];
    o.z = t[x * 4 + 2][y];
    o.w = t[x * 4 + 3][y];
    *(float4*)&h1T[(size_t)(fx + y) * B_DIM + bx + x * 4] = o;
}

// ---------------------------------------------------------------------------
// Per-feature 6-NN batch averaging on TRANSPOSED layout (coalesced I/O).
// Hybrid bitonic sort (registers / shuffles / smem). Measured-good (r13).
// ---------------------------------------------------------------------------
__device__ __forceinline__ void ce_u32(unsigned int& a, unsigned int& b, bool up) {
    unsigned int mn = min(a, b), mx = max(a, b);
    a = up ? mn : mx;
    b = up ? mx : mn;
}

__global__ __launch_bounds__(1024) void knn_mean_kernel(
    const float* __restrict__ h1T, float* __restrict__ outT)
{
    __shared__ unsigned int sv[B_DIM];  // 16 KB

    const int f = blockIdx.x;
    const int t = threadIdx.x;
    const int lane = t & 31;
    const unsigned int i0 = 4u * (unsigned)t;

    unsigned int v[4], myv[4];
    {
        const uint4 hv = *(const uint4*)&h1T[(size_t)f * B_DIM + i0];
        v[0] = hv.x; v[1] = hv.y; v[2] = hv.z; v[3] = hv.w;
#pragma unroll
        for (int e = 0; e < 4; e++) myv[e] = v[e];
    }

    {
        if (v[0] > v[1]) { unsigned int tm = v[0]; v[0] = v[1]; v[1] = tm; }
        if (v[2] < v[3]) { unsigned int tm = v[2]; v[2] = v[3]; v[3] = tm; }
    }
    {
        bool up = (t & 1) == 0;
        ce_u32(v[0], v[2], up); ce_u32(v[1], v[3], up);
        ce_u32(v[0], v[1], up); ce_u32(v[2], v[3], up);
    }

    for (unsigned int k = 8; k <= B_DIM; k <<= 1) {
        const bool up = ((i0 & k) == 0);
        unsigned int j = k >> 1;

        if (j >= 128) {
            *(uint4*)&sv[i0] = make_uint4(v[0], v[1], v[2], v[3]);
            __syncthreads();
            for (; j >= 128; j >>= 1) {
#pragma unroll 2
                for (int p = t; p < B_DIM / 2; p += 1024) {
                    int i = ((p & ~(int)(j - 1)) << 1) | (p & (int)(j - 1));
                    int ixj = i | (int)j;
                    unsigned int a = sv[i];
                    unsigned int b = sv[ixj];
                    bool u2 = ((i & (int)k) == 0);
                    if (u2 ? (a > b) : (a < b)) { sv[i] = b; sv[ixj] = a; }
                }
                __syncthreads();
            }
            uint4 u = *(const uint4*)&sv[i0];
            v[0] = u.x; v[1] = u.y; v[2] = u.z; v[3] = u.w;
        }

        for (; j >= 4; j >>= 1) {
            const unsigned int d = j >> 2;
            const bool keepmin = (up == ((lane & d) == 0));
#pragma unroll
            for (int e = 0; e < 4; e++) {
                unsigned int o = __shfl_xor_sync(0xFFFFFFFFu, v[e], d);
                unsigned int mn = min(v[e], o), mx = max(v[e], o);
                v[e] = keepmin ? mn : mx;
            }
        }

        ce_u32(v[0], v[2], up); ce_u32(v[1], v[3], up);
        ce_u32(v[0], v[1], up); ce_u32(v[2], v[3], up);
    }

    *(uint4*)&sv[i0] = make_uint4(v[0], v[1], v[2], v[3]);
    __syncthreads();

    const float BIG = __int_as_float(0x7f000000);
    float res[4];

#pragma unroll
    for (int e = 0; e < 4; e++) {
        const unsigned int vb = myv[e];
        int lo = 0, hi = B_DIM;
#pragma unroll
        for (int s = 0; s < 12; s++) {
            int mid = (lo + hi) >> 1;
            if (sv[mid] < vb) lo = mid + 1; else hi = mid;
        }
        int p = lo;
        float val = __uint_as_float(vb);
        float sum = val;
        int l = p - 1, r = p + 1;
#pragma unroll
        for (int s = 0; s < 5; s++) {
            float vl = (l >= 0)     ? __uint_as_float(sv[l]) : 0.0f;
            float vr = (r < B_DIM)  ? __uint_as_float(sv[r]) : 0.0f;
            float dl = (l >= 0)     ? (val - vl) : BIG;
            float dr = (r < B_DIM)  ? (vr - val) : BIG;
            if (dl <= dr) { sum += vl; l--; }
            else          { sum += vr; r++; }
        }
        res[e] = sum * (1.0f / 6.0f);
    }

    *(float4*)&outT[(size_t)f * B_DIM + i0] =
        make_float4(res[0], res[1], res[2], res[3]);
}

// ---------------------------------------------------------------------------
// Fully fused PR tail, 256 threads (2 warps/SMSP latency cover):
//   pr1 = relu(pr0T^T @ Wpr^T + bpr); h2 = relu(pr1 @ W2^T + b2);
//   out = h2 @ Wo^T + bo. Shared memory phase-aliased through one pool.
// ---------------------------------------------------------------------------
__global__ __launch_bounds__(256) void pr_tail_fused_kernel(
    const float* __restrict__ AT,    // pr0T [128][4096]
    const float* __restrict__ Wpr,   // [128][128] K-major
    const float* __restrict__ bpr,   // [128]
    const float* __restrict__ W2,    // [64][128]
    const float* __restrict__ b2,    // [64]
    const float* __restrict__ Wo,    // [2,64]
    const float* __restrict__ bo,    // [2]
    float* __restrict__ out)         // [4096,2]
{
    constexpr int BM = 32, BK = 32, K = H1_DIM, M = B_DIM, NB = K / BK;

    __shared__ __align__(16) char pool[33920];
    float (*As2)[34]  = (float(*)[34])pool;                  // [k][m]
    float (*Bs)[132]  = (float(*)[132])(pool + 4352);        // [k][n]
    float (*prs)[132] = (float(*)[132])pool;                 // pr1 tile [m][k]
    float (*w2c)[68]  = (float(*)[68])(pool + 16896);        // W2 chunk [k][c]
    float (*h2s)[65]  = (float(*)[65])(pool + 25600);        // h2 tile
    __shared__ float wos[O_DIM * H2_DIM];
    __shared__ float bprs[H1_DIM];
    __shared__ float b2s[H2_DIM];
    __shared__ float bos[O_DIM];

    const int tid = threadIdx.x;
    const int tx = tid & 7;        // col group (8)
    const int ty = tid >> 3;       // row 0..31
    const int row0 = blockIdx.x * BM;
    const int l_kq = tid & 7;
    const int l_r  = tid >> 3;     // 0..31

    if (tid < O_DIM * H2_DIM) wos[tid] = Wo[tid];
    if (tid < H1_DIM) bprs[tid] = bpr[tid];
    if (tid < H2_DIM) b2s[tid] = b2[tid];
    if (tid < O_DIM)  bos[tid] = bo[tid];

    unsigned long long acc[8];
#pragma unroll
    for (int j = 0; j < 8; j++) acc[j] = 0ull;

    float4 pa, pb[4];
    pa = *(const float4*)&AT[(size_t)l_r * M + row0 + l_kq * 4];
#pragma unroll
    for (int it = 0; it < 4; it++)
        pb[it] = *(const float4*)&Wpr[(size_t)(l_r + it * 32) * K + l_kq * 4];

    {
        As2[l_r][l_kq * 4 + 0] = pa.x; As2[l_r][l_kq * 4 + 1] = pa.y;
        As2[l_r][l_kq * 4 + 2] = pa.z; As2[l_r][l_kq * 4 + 3] = pa.w;
#pragma unroll
        for (int it = 0; it < 4; it++) {
            int f = l_r + it * 32;
            Bs[l_kq * 4 + 0][f] = pb[it].x; Bs[l_kq * 4 + 1][f] = pb[it].y;
            Bs[l_kq * 4 + 2][f] = pb[it].z; Bs[l_kq * 4 + 3][f] = pb[it].w;
        }
    }
    __syncthreads();

    for (int kb = 0; kb < NB; kb++) {
        const bool more = (kb + 1 < NB);
        if (more) {
            const int k0 = (kb + 1) * BK;
            pa = *(const float4*)&AT[(size_t)(k0 + l_r) * M + row0 + l_kq * 4];
#pragma unroll
            for (int it = 0; it < 4; it++)
                pb[it] = *(const float4*)&Wpr[(size_t)(l_r + it * 32) * K + k0 + l_kq * 4];
        }

#pragma unroll
        for (int kk = 0; kk < BK; kk++) {
            float a = As2[kk][ty];
            unsigned long long ap = pk2(a, a);
#pragma unroll
            for (int q = 0; q < 4; q++) {
                ulonglong2 bq = *(const ulonglong2*)&Bs[kk][q * 32 + tx * 4];
                ffma2(acc[q * 2 + 0], ap, bq.x);
                ffma2(acc[q * 2 + 1], ap, bq.y);
            }
        }
        __syncthreads();
        if (more) {
            As2[l_r][l_kq * 4 + 0] = pa.x; As2[l_r][l_kq * 4 + 1] = pa.y;
            As2[l_r][l_kq * 4 + 2] = pa.z; As2[l_r][l_kq * 4 + 3] = pa.w;
#pragma unroll
            for (int it = 0; it < 4; it++) {
                int f = l_r + it * 32;
                Bs[l_kq * 4 + 0][f] = pb[it].x; Bs[l_kq * 4 + 1][f] = pb[it].y;
                Bs[l_kq * 4 + 2][f] = pb[it].z; Bs[l_kq * 4 + 3][f] = pb[it].w;
            }
            __syncthreads();
        }
    }

    // pr1 row -> prs (aliases pool) with bias + ReLU
#pragma unroll
    for (int q = 0; q < 4; q++) {
        const int c = q * 32 + tx * 4;
        float2 p0 = upk2(acc[q * 2 + 0]);
        float2 p1 = upk2(acc[q * 2 + 1]);
        prs[ty][c + 0] = fmaxf(p0.x + bprs[c + 0], 0.0f);
        prs[ty][c + 1] = fmaxf(p0.y + bprs[c + 1], 0.0f);
        prs[ty][c + 2] = fmaxf(p1.x + bprs[c + 2], 0.0f);
        prs[ty][c + 3] = fmaxf(p1.y + bprs[c + 3], 0.0f);
    }
    __syncthreads();

    // h2 = relu(prs @ W2^T + b2): each thread 2 rows x 4 cols, FFMA2
    const int tx2 = tid & 15;
    const int tyB = tid >> 4;
    unsigned long long acc2[2][2];
#pragma unroll
    for (int i = 0; i < 2; i++) { acc2[i][0] = 0ull; acc2[i][1] = 0ull; }

    for (int kb2 = 0; kb2 < 4; kb2++) {
#pragma unroll
        for (int it = 0; it < 2; it++) {
            int c = l_r + it * 32;
            float4 w = *(const float4*)&W2[(size_t)c * K + kb2 * 32 + l_kq * 4];
            w2c[l_kq * 4 + 0][c] = w.x;
            w2c[l_kq * 4 + 1][c] = w.y;
            w2c[l_kq * 4 + 2][c] = w.z;
            w2c[l_kq * 4 + 3][c] = w.w;
        }
        __syncthreads();
#pragma unroll
        for (int kk = 0; kk < 32; kk++) {
            ulonglong2 wv = *(const ulonglong2*)&w2c[kk][tx2 * 4];
            float p0 = prs[tyB * 2 + 0][kb2 * 32 + kk];
            float p1 = prs[tyB * 2 + 1][kb2 * 32 + kk];
            unsigned long long a0 = pk2(p0, p0);
            unsigned long long a1 = pk2(p1, p1);
            ffma2(acc2[0][0], a0, wv.x); ffma2(acc2[0][1], a0, wv.y);
            ffma2(acc2[1][0], a1, wv.x); ffma2(acc2[1][1], a1, wv.y);
        }
        __syncthreads();
    }

#pragma unroll
    for (int i = 0; i < 2; i++) {
        float2 q0 = upk2(acc2[i][0]);
        float2 q1 = upk2(acc2[i][1]);
        const int c = tx2 * 4;
        h2s[tyB * 2 + i][c + 0] = fmaxf(q0.x + b2s[c + 0], 0.0f);
        h2s[tyB * 2 + i][c + 1] = fmaxf(q0.y + b2s[c + 1], 0.0f);
        h2s[tyB * 2 + i][c + 2] = fmaxf(q1.x + b2s[c + 2], 0.0f);
        h2s[tyB * 2 + i][c + 3] = fmaxf(q1.y + b2s[c + 3], 0.0f);
    }
    __syncthreads();

    if (tid < BM * O_DIM) {
        int r = tid >> 1, o = tid & 1;
        float s = 0.0f;
        const float* w = &wos[o * H2_DIM];
#pragma unroll
        for (int k = 0; k < H2_DIM; k++)
            s = fmaf(h2s[r][k], w[k], s);
        out[(size_t)(row0 + r) * O_DIM + o] = s + bos[o];
    }
}

// ---------------------------------------------------------------------------
extern "C" void kernel_launch(void* const* d_in, const int* in_sizes, int n_in,
                              void* d_out, int out_size)
{
    const float* x   = (const float*)d_in[0];
    const float* W1  = (const float*)d_in[1];
    const float* b1  = (const float*)d_in[2];
    const float* Wpr = (const float*)d_in[3];
    const float* bpr = (const float*)d_in[4];
    const float* W2  = (const float*)d_in[5];
    const float* b2  = (const float*)d_in[6];
    const float* Wo  = (const float*)d_in[7];
    const float* bo  = (const float*)d_in[8];
    float* out = (float*)d_out;

    float *part, *h1T, *pr0T;
    cudaGetSymbolAddress((void**)&part, g_part);
    cudaGetSymbolAddress((void**)&h1T,  g_h1T);
    cudaGetSymbolAddress((void**)&pr0T, g_pr0T);

    // 1) gemm1 K-split, BM=64 high-density tile (512 CTAs)
    gemm_split_kernel<<<dim3(B_DIM / 64, H1_DIM / 64, KSPLIT), 128>>>(
        x, W1, part, B_DIM, H1_DIM, KCHUNK, D_DIM);
    // 2) combine partials + b1 + relu, write transposed h1T [128][4096]
    combine_transpose_kernel<<<dim3(B_DIM / 32, H1_DIM / 32), 256>>>(
        part, b1, h1T);
    // 3) knn on transposed layout (coalesced load + store)
    knn_mean_kernel<<<H1_DIM, 1024>>>(h1T, pr0T);
    // 4) fused pr1 + h2 + output projection (256 threads)
    pr_tail_fused_kernel<<<B_DIM / 32, 256>>>(
        pr0T, Wpr, bpr, W2, b2, Wo, bo, out);
}

// round 17
// speedup vs baseline: 1.2904x; 1.0816x over previous
#include <cuda_runtime.h>
#include <cuda_bf16.h>
#include <cstdint>

#define B_DIM 4096
#define D_DIM 1024
#define H1_DIM 128
#define H2_DIM 64
#define O_DIM 2
#define KSPLIT 4
#define KCHUNK (D_DIM / KSPLIT)   // 256

// Scratch (no cudaMalloc allowed)
__device__ float g_part[KSPLIT * B_DIM * H1_DIM];  // gemm1 partials [z][b][f]
__device__ float g_h1T[H1_DIM * B_DIM];            // h1 transposed [f][b]
__device__ float g_pr0T[H1_DIM * B_DIM];           // knn output transposed [f][b]

// ---------------------------------------------------------------------------
// Packed fp32x2 helpers (Blackwell FFMA2 — only reachable via PTX)
// ---------------------------------------------------------------------------
__device__ __forceinline__ unsigned long long pk2(float x, float y) {
    unsigned long long r;
    asm("mov.b64 %0, {%1, %2};" : "=l"(r) : "f"(x), "f"(y));
    return r;
}
__device__ __forceinline__ void ffma2(unsigned long long& d,
                                      unsigned long long a,
                                      unsigned long long b) {
    asm("fma.rn.f32x2 %0, %1, %2, %0;" : "+l"(d) : "l"(a), "l"(b));
}
__device__ __forceinline__ float2 upk2(unsigned long long v) {
    float2 f;
    asm("mov.b64 {%0, %1}, %2;" : "=f"(f.x), "=f"(f.y) : "l"(v));
    return f;
}

// ---------------------------------------------------------------------------
// High-density SGEMM (NN) for gemm1 K-split.  (Measured-good in 74.2us run.)
// BM=64, BN=64, BK=32, 128 threads, 4 rows x 8 cols per thread.
// A staged TRANSPOSED in smem ([k][m], stride 68): 3 LDS.128 per 16 FFMA2.
// ---------------------------------------------------------------------------
__global__ __launch_bounds__(128) void gemm_split_kernel(
    const float* __restrict__ A, const float* __restrict__ Bm,
    float* __restrict__ C, int M, int N, int Kloop, int lda)
{
    constexpr int BK = 32;
    __shared__ float As2[BK][68];   // [k][m] transposed
    __shared__ float Bs[BK][68];    // [k][n]

    const int tid = threadIdx.x;
    const int tx = tid & 7;         // 8 col groups
    const int ty = tid >> 3;        // 16 row groups -> rows ty*4 .. +3
    const int row0 = blockIdx.x * 64;
    const int col0 = blockIdx.y * 64;
    const int z = blockIdx.z;

    const float* Ap = A + (size_t)z * Kloop;
    const float* Bp = Bm + (size_t)col0 * lda + (size_t)z * Kloop;
    float* Cz = C + (size_t)z * M * N;

    const int l_kq = tid & 7;
    const int l_r  = tid >> 3;      // 0..15

    unsigned long long acc[4][4];
#pragma unroll
    for (int i = 0; i < 4; i++)
#pragma unroll
        for (int j = 0; j < 4; j++) acc[i][j] = 0ull;

    const int NB = Kloop / BK;
    float4 pa[4], pb[4];

#pragma unroll
    for (int it = 0; it < 4; it++)
        pa[it] = *(const float4*)&Ap[(size_t)(row0 + l_r + it * 16) * lda + l_kq * 4];
#pragma unroll
    for (int it = 0; it < 4; it++)
        pb[it] = *(const float4*)&Bp[(size_t)(l_r + it * 16) * lda + l_kq * 4];

#pragma unroll
    for (int it = 0; it < 4; it++) {
        int r = l_r + it * 16;
        As2[l_kq * 4 + 0][r] = pa[it].x; As2[l_kq * 4 + 1][r] = pa[it].y;
        As2[l_kq * 4 + 2][r] = pa[it].z; As2[l_kq * 4 + 3][r] = pa[it].w;
    }
#pragma unroll
    for (int it = 0; it < 4; it++) {
        int f = l_r + it * 16;
        Bs[l_kq * 4 + 0][f] = pb[it].x; Bs[l_kq * 4 + 1][f] = pb[it].y;
        Bs[l_kq * 4 + 2][f] = pb[it].z; Bs[l_kq * 4 + 3][f] = pb[it].w;
    }
    __syncthreads();

    for (int kb = 0; kb < NB; kb++) {
        const bool more = (kb + 1 < NB);
        if (more) {
            const int k0 = (kb + 1) * BK;
#pragma unroll
            for (int it = 0; it < 4; it++)
                pa[it] = *(const float4*)&Ap[(size_t)(row0 + l_r + it * 16) * lda + k0 + l_kq * 4];
#pragma unroll
            for (int it = 0; it < 4; it++)
                pb[it] = *(const float4*)&Bp[(size_t)(l_r + it * 16) * lda + k0 + l_kq * 4];
        }

#pragma unroll
        for (int kk = 0; kk < BK; kk++) {
            float4 a = *(const float4*)&As2[kk][ty * 4];
            ulonglong2 b01 = *(const ulonglong2*)&Bs[kk][tx * 4];
            ulonglong2 b23 = *(const ulonglong2*)&Bs[kk][32 + tx * 4];
            unsigned long long ap0 = pk2(a.x, a.x);
            unsigned long long ap1 = pk2(a.y, a.y);
            unsigned long long ap2 = pk2(a.z, a.z);
            unsigned long long ap3 = pk2(a.w, a.w);
            ffma2(acc[0][0], ap0, b01.x); ffma2(acc[0][1], ap0, b01.y);
            ffma2(acc[0][2], ap0, b23.x); ffma2(acc[0][3], ap0, b23.y);
            ffma2(acc[1][0], ap1, b01.x); ffma2(acc[1][1], ap1, b01.y);
            ffma2(acc[1][2], ap1, b23.x); ffma2(acc[1][3], ap1, b23.y);
            ffma2(acc[2][0], ap2, b01.x); ffma2(acc[2][1], ap2, b01.y);
            ffma2(acc[2][2], ap2, b23.x); ffma2(acc[2][3], ap2, b23.y);
            ffma2(acc[3][0], ap3, b01.x); ffma2(acc[3][1], ap3, b01.y);
            ffma2(acc[3][2], ap3, b23.x); ffma2(acc[3][3], ap3, b23.y);
        }
        __syncthreads();
        if (more) {
#pragma unroll
            for (int it = 0; it < 4; it++) {
                int r = l_r + it * 16;
                As2[l_kq * 4 + 0][r] = pa[it].x; As2[l_kq * 4 + 1][r] = pa[it].y;
                As2[l_kq * 4 + 2][r] = pa[it].z; As2[l_kq * 4 + 3][r] = pa[it].w;
            }
#pragma unroll
            for (int it = 0; it < 4; it++) {
                int f = l_r + it * 16;
                Bs[l_kq * 4 + 0][f] = pb[it].x; Bs[l_kq * 4 + 1][f] = pb[it].y;
                Bs[l_kq * 4 + 2][f] = pb[it].z; Bs[l_kq * 4 + 3][f] = pb[it].w;
            }
            __syncthreads();
        }
    }

    // Row-major coalesced epilogue (raw partials, no bias)
#pragma unroll
    for (int r = 0; r < 4; r++) {
        const int row = row0 + ty * 4 + r;
#pragma unroll
        for (int half = 0; half < 2; half++) {
            const int c = col0 + half * 32 + tx * 4;
            float2 p0 = upk2(acc[r][half * 2 + 0]);
            float2 p1 = upk2(acc[r][half * 2 + 1]);
            *(float4*)&Cz[(size_t)row * N + c] =
                make_float4(p0.x, p0.y, p1.x, p1.y);
        }
    }
}

// ---------------------------------------------------------------------------
// Combine K-split partials + bias + ReLU, writing h1 TRANSPOSED.
// (Measured-good.)
// ---------------------------------------------------------------------------
__global__ __launch_bounds__(256) void combine_transpose_kernel(
    const float* __restrict__ part, const float* __restrict__ b1,
    float* __restrict__ h1T)
{
    __shared__ float t[32][33];
    const int bx = blockIdx.x * 32;
    const int fx = blockIdx.y * 32;
    const int tid = threadIdx.x;
    const int x = tid & 7;
    const int y = tid >> 3;

    const size_t BH = (size_t)B_DIM * H1_DIM;
    const size_t idx = (size_t)(bx + y) * H1_DIM + fx + x * 4;
    float4 s  = *(const float4*)&part[idx];
    float4 p1 = *(const float4*)&part[idx + BH];
    float4 p2 = *(const float4*)&part[idx + 2 * BH];
    float4 p3 = *(const float4*)&part[idx + 3 * BH];
    s.x += p1.x; s.y += p1.y; s.z += p1.z; s.w += p1.w;
    s.x += p2.x; s.y += p2.y; s.z += p2.z; s.w += p2.w;
    s.x += p3.x; s.y += p3.y; s.z += p3.z; s.w += p3.w;
    const float4 bv = *(const float4*)&b1[fx + x * 4];
    t[y][x * 4 + 0] = fmaxf(s.x + bv.x, 0.0f);
    t[y][x * 4 + 1] = fmaxf(s.y + bv.y, 0.0f);
    t[y][x * 4 + 2] = fmaxf(s.z + bv.z, 0.0f);
    t[y][x * 4 + 3] = fmaxf(s.w + bv.w, 0.0f);
    __syncthreads();

    float4 o;
    o.x = t[x * 4 + 0][y];
    o.y = t[x * 4 + 1][y];
    o.z = t[x * 4 + 2][y];
    o.w = t[x * 4 + 3][y];
    *(float4*)&h1T[(size_t)(fx + y) * B_DIM + bx + x * 4] = o;
}

// ---------------------------------------------------------------------------
// Per-feature 6-NN batch averaging on TRANSPOSED layout (measured-good).
// ---------------------------------------------------------------------------
__device__ __forceinline__ void ce_u32(unsigned int& a, unsigned int& b, bool up) {
    unsigned int mn = min(a, b), mx = max(a, b);
    a = up ? mn : mx;
    b = up ? mx : mn;
}

__global__ __launch_bounds__(1024) void knn_mean_kernel(
    const float* __restrict__ h1T, float* __restrict__ outT)
{
    __shared__ unsigned int sv[B_DIM];  // 16 KB

    const int f = blockIdx.x;
    const int t = threadIdx.x;
    const int lane = t & 31;
    const unsigned int i0 = 4u * (unsigned)t;

    unsigned int v[4], myv[4];
    {
        const uint4 hv = *(const uint4*)&h1T[(size_t)f * B_DIM + i0];
        v[0] = hv.x; v[1] = hv.y; v[2] = hv.z; v[3] = hv.w;
#pragma unroll
        for (int e = 0; e < 4; e++) myv[e] = v[e];
    }

    {
        if (v[0] > v[1]) { unsigned int tm = v[0]; v[0] = v[1]; v[1] = tm; }
        if (v[2] < v[3]) { unsigned int tm = v[2]; v[2] = v[3]; v[3] = tm; }
    }
    {
        bool up = (t & 1) == 0;
        ce_u32(v[0], v[2], up); ce_u32(v[1], v[3], up);
        ce_u32(v[0], v[1], up); ce_u32(v[2], v[3], up);
    }

    for (unsigned int k = 8; k <= B_DIM; k <<= 1) {
        const bool up = ((i0 & k) == 0);
        unsigned int j = k >> 1;

        if (j >= 128) {
            *(uint4*)&sv[i0] = make_uint4(v[0], v[1], v[2], v[3]);
            __syncthreads();
            for (; j >= 128; j >>= 1) {
#pragma unroll 2
                for (int p = t; p < B_DIM / 2; p += 1024) {
                    int i = ((p & ~(int)(j - 1)) << 1) | (p & (int)(j - 1));
                    int ixj = i | (int)j;
                    unsigned int a = sv[i];
                    unsigned int b = sv[ixj];
                    bool u2 = ((i & (int)k) == 0);
                    if (u2 ? (a > b) : (a < b)) { sv[i] = b; sv[ixj] = a; }
                }
                __syncthreads();
            }
            uint4 u = *(const uint4*)&sv[i0];
            v[0] = u.x; v[1] = u.y; v[2] = u.z; v[3] = u.w;
        }

        for (; j >= 4; j >>= 1) {
            const unsigned int d = j >> 2;
            const bool keepmin = (up == ((lane & d) == 0));
#pragma unroll
            for (int e = 0; e < 4; e++) {
                unsigned int o = __shfl_xor_sync(0xFFFFFFFFu, v[e], d);
                unsigned int mn = min(v[e], o), mx = max(v[e], o);
                v[e] = keepmin ? mn : mx;
            }
        }

        ce_u32(v[0], v[2], up); ce_u32(v[1], v[3], up);
        ce_u32(v[0], v[1], up); ce_u32(v[2], v[3], up);
    }

    *(uint4*)&sv[i0] = make_uint4(v[0], v[1], v[2], v[3]);
    __syncthreads();

    const float BIG = __int_as_float(0x7f000000);
    float res[4];

#pragma unroll
    for (int e = 0; e < 4; e++) {
        const unsigned int vb = myv[e];
        int lo = 0, hi = B_DIM;
#pragma unroll
        for (int s = 0; s < 12; s++) {
            int mid = (lo + hi) >> 1;
            if (sv[mid] < vb) lo = mid + 1; else hi = mid;
        }
        int p = lo;
        float val = __uint_as_float(vb);
        float sum = val;
        int l = p - 1, r = p + 1;
#pragma unroll
        for (int s = 0; s < 5; s++) {
            float vl = (l >= 0)     ? __uint_as_float(sv[l]) : 0.0f;
            float vr = (r < B_DIM)  ? __uint_as_float(sv[r]) : 0.0f;
            float dl = (l >= 0)     ? (val - vl) : BIG;
            float dr = (r < B_DIM)  ? (vr - val) : BIG;
            if (dl <= dr) { sum += vl; l--; }
            else          { sum += vr; r++; }
        }
        res[e] = sum * (1.0f / 6.0f);
    }

    *(float4*)&outT[(size_t)f * B_DIM + i0] =
        make_float4(res[0], res[1], res[2], res[3]);
}

// ---------------------------------------------------------------------------
// Fused PR tail v3: 128 threads, high-density phase 1 (4 rows x 8 cols per
// thread, A staged [k][m] -> 3 LDS.128 per 16 FFMA2 — the recipe that fixed
// gemm_split). Phases 2/3 are the r13 measured shapes.
//   pr1 = relu(pr0T^T @ Wpr^T + bpr); h2 = relu(pr1 @ W2^T + b2);
//   out = h2 @ Wo^T + bo.  128 CTAs. Smem phase-aliased via one pool.
// ---------------------------------------------------------------------------
__global__ __launch_bounds__(128) void pr_tail_fused_kernel(
    const float* __restrict__ AT,    // pr0T [128][4096]
    const float* __restrict__ Wpr,   // [128][128] K-major
    const float* __restrict__ bpr,   // [128]
    const float* __restrict__ W2,    // [64][128]
    const float* __restrict__ b2,    // [64]
    const float* __restrict__ Wo,    // [2,64]
    const float* __restrict__ bo,    // [2]
    float* __restrict__ out)         // [4096,2]
{
    constexpr int BM = 32, BK = 32, K = H1_DIM, M = B_DIM, NB = K / BK;

    // Pool: phase1 As2[32][36] (4608) + Bs[32][132] (16896) = 21504
    //       phase2 prs[32][132] (16896) + w2c[32][68] (8704) + h2s[32][65] (8320) = 33920
    __shared__ __align__(16) char pool[33920];
    float (*As2)[36]  = (float(*)[36])pool;                  // [k][m]
    float (*Bs)[132]  = (float(*)[132])(pool + 4608);        // [k][n]
    float (*prs)[132] = (float(*)[132])pool;                 // pr1 tile [m][k]
    float (*w2c)[68]  = (float(*)[68])(pool + 16896);        // W2 chunk [k][c]
    float (*h2s)[65]  = (float(*)[65])(pool + 25600);        // h2 tile
    __shared__ float wos[O_DIM * H2_DIM];
    __shared__ float bprs[H1_DIM];
    __shared__ float b2s[H2_DIM];
    __shared__ float bos[O_DIM];

    const int tid = threadIdx.x;
    const int tx  = tid & 15;       // 16 col groups; cols {tx*4, 64+tx*4}
    const int tyR = (tid >> 4) * 4; // 8 row groups -> rows tyR..tyR+3
    const int row0 = blockIdx.x * BM;
    const int l_kq = tid & 7;       // float4 along k
    const int l_r  = tid >> 3;      // 0..15

    if (tid < O_DIM * H2_DIM) wos[tid] = Wo[tid];
    bprs[tid] = bpr[tid];           // 128 threads, 128 elems
    if (tid < H2_DIM) b2s[tid] = b2[tid];
    if (tid < O_DIM)  bos[tid] = bo[tid];

    unsigned long long acc[4][4];
#pragma unroll
    for (int i = 0; i < 4; i++)
#pragma unroll
        for (int j = 0; j < 4; j++) acc[i][j] = 0ull;

    // Loaders: A tile 32k x 32m from AT[k][m] (coalesced along m):
    //   k = l_r + it*16 (it 0..1), m = row0 + l_kq*4? -> need m float4 groups:
    //   use l_m4 = tid & 7 (8 groups = 32 m), l_k = tid >> 3 (16), 2 iters.
    // B tile 32k x 128n from Wpr[n][k]: l_kq float4 along k, n = l_r + it*16, 8 iters.
    float4 pa[2], pb[8];
#pragma unroll
    for (int it = 0; it < 2; it++)
        pa[it] = *(const float4*)&AT[(size_t)(l_r + it * 16) * M + row0 + l_kq * 4];
#pragma unroll
    for (int it = 0; it < 8; it++)
        pb[it] = *(const float4*)&Wpr[(size_t)(l_r + it * 16) * K + l_kq * 4];

    {
#pragma unroll
        for (int it = 0; it < 2; it++) {
            int k = l_r + it * 16;
            *(float4*)&As2[k][l_kq * 4] = pa[it];   // [k][m], aligned (36*4=144)
        }
#pragma unroll
        for (int it = 0; it < 8; it++) {
            int f = l_r + it * 16;
            Bs[l_kq * 4 + 0][f] = pb[it].x; Bs[l_kq * 4 + 1][f] = pb[it].y;
            Bs[l_kq * 4 + 2][f] = pb[it].z; Bs[l_kq * 4 + 3][f] = pb[it].w;
        }
    }
    __syncthreads();

    for (int kb = 0; kb < NB; kb++) {
        const bool more = (kb + 1 < NB);
        if (more) {
            const int k0 = (kb + 1) * BK;
#pragma unroll
            for (int it = 0; it < 2; it++)
                pa[it] = *(const float4*)&AT[(size_t)(k0 + l_r + it * 16) * M + row0 + l_kq * 4];
#pragma unroll
            for (int it = 0; it < 8; it++)
                pb[it] = *(const float4*)&Wpr[(size_t)(l_r + it * 16) * K + k0 + l_kq * 4];
        }

#pragma unroll
        for (int kk = 0; kk < BK; kk++) {
            float4 a = *(const float4*)&As2[kk][tyR];           // 4 rows
            ulonglong2 b0 = *(const ulonglong2*)&Bs[kk][tx * 4];        // cols tx*4..+3
            ulonglong2 b1 = *(const ulonglong2*)&Bs[kk][64 + tx * 4];   // cols 64+tx*4..+3
            unsigned long long ap0 = pk2(a.x, a.x);
            unsigned long long ap1 = pk2(a.y, a.y);
            unsigned long long ap2 = pk2(a.z, a.z);
            unsigned long long ap3 = pk2(a.w, a.w);
            ffma2(acc[0][0], ap0, b0.x); ffma2(acc[0][1], ap0, b0.y);
            ffma2(acc[0][2], ap0, b1.x); ffma2(acc[0][3], ap0, b1.y);
            ffma2(acc[1][0], ap1, b0.x); ffma2(acc[1][1], ap1, b0.y);
            ffma2(acc[1][2], ap1, b1.x); ffma2(acc[1][3], ap1, b1.y);
            ffma2(acc[2][0], ap2, b0.x); ffma2(acc[2][1], ap2, b0.y);
            ffma2(acc[2][2], ap2, b1.x); ffma2(acc[2][3], ap2, b1.y);
            ffma2(acc[3][0], ap3, b0.x); ffma2(acc[3][1], ap3, b0.y);
            ffma2(acc[3][2], ap3, b1.x); ffma2(acc[3][3], ap3, b1.y);
        }
        __syncthreads();
        if (more) {
#pragma unroll
            for (int it = 0; it < 2; it++) {
                int k = l_r + it * 16;
                *(float4*)&As2[k][l_kq * 4] = pa[it];
            }
#pragma unroll
            for (int it = 0; it < 8; it++) {
                int f = l_r + it * 16;
                Bs[l_kq * 4 + 0][f] = pb[it].x; Bs[l_kq * 4 + 1][f] = pb[it].y;
                Bs[l_kq * 4 + 2][f] = pb[it].z; Bs[l_kq * 4 + 3][f] = pb[it].w;
            }
            __syncthreads();
        }
    }
    // (mainloop ended on __syncthreads: As2/Bs dead, pool reusable as prs)

    // pr1 tile -> prs[m][k] with bias + ReLU (float4 stores, bank-clean)
#pragma unroll
    for (int r = 0; r < 4; r++) {
        const int row = tyR + r;
#pragma unroll
        for (int half = 0; half < 2; half++) {
            const int c = half * 64 + tx * 4;
            float2 p0 = upk2(acc[r][half * 2 + 0]);
            float2 p1 = upk2(acc[r][half * 2 + 1]);
            float4 v;
            v.x = fmaxf(p0.x + bprs[c + 0], 0.0f);
            v.y = fmaxf(p0.y + bprs[c + 1], 0.0f);
            v.z = fmaxf(p1.x + bprs[c + 2], 0.0f);
            v.w = fmaxf(p1.y + bprs[c + 3], 0.0f);
            *(float4*)&prs[row][c] = v;
        }
    }
    __syncthreads();

    // h2 = relu(prs @ W2^T + b2): r13 measured shape (4 rows x 4 cols/thread)
    const int tx2 = tid & 15;   // cols tx2*4 .. +3
    const int tyB = tid >> 4;   // rows tyB*4 .. +3
    float acc2[4][4];
#pragma unroll
    for (int i = 0; i < 4; i++)
#pragma unroll
        for (int j = 0; j < 4; j++) acc2[i][j] = 0.0f;

    for (int kb2 = 0; kb2 < 4; kb2++) {
        // load W2 chunk [64 c][32 k] transposed into w2c[k][c]
#pragma unroll
        for (int it = 0; it < 4; it++) {
            int c = l_r + it * 16;
            float4 w = *(const float4*)&W2[(size_t)c * K + kb2 * 32 + l_kq * 4];
            w2c[l_kq * 4 + 0][c] = w.x;
            w2c[l_kq * 4 + 1][c] = w.y;
            w2c[l_kq * 4 + 2][c] = w.z;
            w2c[l_kq * 4 + 3][c] = w.w;
        }
        __syncthreads();
#pragma unroll
        for (int kk = 0; kk < 32; kk++) {
            float4 wv = *(const float4*)&w2c[kk][tx2 * 4];
            float p0 = prs[tyB * 4 + 0][kb2 * 32 + kk];
            float p1 = prs[tyB * 4 + 1][kb2 * 32 + kk];
            float p2 = prs[tyB * 4 + 2][kb2 * 32 + kk];
            float p3 = prs[tyB * 4 + 3][kb2 * 32 + kk];
            acc2[0][0] = fmaf(p0, wv.x, acc2[0][0]); acc2[0][1] = fmaf(p0, wv.y, acc2[0][1]);
            acc2[0][2] = fmaf(p0, wv.z, acc2[0][2]); acc2[0][3] = fmaf(p0, wv.w, acc2[0][3]);
            acc2[1][0] = fmaf(p1, wv.x, acc2[1][0]); acc2[1][1] = fmaf(p1, wv.y, acc2[1][1]);
            acc2[1][2] = fmaf(p1, wv.z, acc2[1][2]); acc2[1][3] = fmaf(p1, wv.w, acc2[1][3]);
            acc2[2][0] = fmaf(p2, wv.x, acc2[2][0]); acc2[2][1] = fmaf(p2, wv.y, acc2[2][1]);
            acc2[2][2] = fmaf(p2, wv.z, acc2[2][2]); acc2[2][3] = fmaf(p2, wv.w, acc2[2][3]);
            acc2[3][0] = fmaf(p3, wv.x, acc2[3][0]); acc2[3][1] = fmaf(p3, wv.y, acc2[3][1]);
            acc2[3][2] = fmaf(p3, wv.z, acc2[3][2]); acc2[3][3] = fmaf(p3, wv.w, acc2[3][3]);
        }
        __syncthreads();
    }

    // h2s with bias + ReLU
#pragma unroll
    for (int i = 0; i < 4; i++)
#pragma unroll
        for (int j = 0; j < 4; j++) {
            int c = tx2 * 4 + j;
            h2s[tyB * 4 + i][c] = fmaxf(acc2[i][j] + b2s[c], 0.0f);
        }
    __syncthreads();

    // Projection: 64 work items (32 rows x 2 outs)
    if (tid < BM * O_DIM) {
        int r = tid >> 1, o = tid & 1;
        float s = 0.0f;
        const float* w = &wos[o * H2_DIM];
#pragma unroll
        for (int k = 0; k < H2_DIM; k++)
            s = fmaf(h2s[r][k], w[k], s);
        out[(size_t)(row0 + r) * O_DIM + o] = s + bos[o];
    }
}

// ---------------------------------------------------------------------------
extern "C" void kernel_launch(void* const* d_in, const int* in_sizes, int n_in,
                              void* d_out, int out_size)
{
    const float* x   = (const float*)d_in[0];
    const float* W1  = (const float*)d_in[1];
    const float* b1  = (const float*)d_in[2];
    const float* Wpr = (const float*)d_in[3];
    const float* bpr = (const float*)d_in[4];
    const float* W2  = (const float*)d_in[5];
    const float* b2  = (const float*)d_in[6];
    const float* Wo  = (const float*)d_in[7];
    const float* bo  = (const float*)d_in[8];
    float* out = (float*)d_out;

    float *part, *h1T, *pr0T;
    cudaGetSymbolAddress((void**)&part, g_part);
    cudaGetSymbolAddress((void**)&h1T,  g_h1T);
    cudaGetSymbolAddress((void**)&pr0T, g_pr0T);

    // 1) gemm1 K-split, BM=64 high-density tile (512 CTAs)
    gemm_split_kernel<<<dim3(B_DIM / 64, H1_DIM / 64, KSPLIT), 128>>>(
        x, W1, part, B_DIM, H1_DIM, KCHUNK, D_DIM);
    // 2) combine partials + b1 + relu, write transposed h1T [128][4096]
    combine_transpose_kernel<<<dim3(B_DIM / 32, H1_DIM / 32), 256>>>(
        part, b1, h1T);
    // 3) knn on transposed layout (coalesced load + store)
    knn_mean_kernel<<<H1_DIM, 1024>>>(h1T, pr0T);
    // 4) fused pr1 + h2 + output projection (128 thr, high-density phase 1)
    pr_tail_fused_kernel<<<B_DIM / 32, 128>>>(
        pr0T, Wpr, bpr, W2, b2, Wo, bo, out);
}